// round 11
// baseline (speedup 1.0000x reference)
#include <cuda_runtime.h>
#include <cuda_fp16.h>
#include <cuda_bf16.h>
#include <mma.h>
#include <cstdint>

using namespace nvcuda;

// ---------------- problem constants ----------------
#define NNODES   100000
#define DIN      512
#define DOUT     256
#define EDGES_MAX 3200000
#define KEEP_THRESH 7549747u          // 0.9f == 7549747 * 2^-23 exactly
#define INV_KEEP (1.0f/0.9f)
#define SCAN_BLK  98

// GEMM tiling (wmma HMMA path, compute_103-safe)
#define BMT 64
#define BNT 256
#define KC  32
#define NCHUNK (DIN / KC)             // 16
#define LDS_T 36                      // row stride elems (72B; 8B-aligned rows,
                                      // frag ptrs at 16-row multiples -> 1152B aligned)
// dynamic smem layout (elems of bf16), double-buffered
#define A_SEC (BMT * LDS_T)           // 2304
#define B_SEC (BNT * LDS_T)           // 9216
#define BUF_SEC (2 * A_SEC + 2 * B_SEC)          // one stage: Ahi,Alo,Bhi,Blo
#define SMEM_ELEMS (2 * BUF_SEC)                 // 46080 elems = 92160 B

// scratch
__device__ __half         g_h[(size_t)NNODES * DOUT];   // 51.2 MB fp16
__device__ __nv_bfloat16  g_Bhi[DOUT * DIN];            // W split, K-major [n][k]
__device__ __nv_bfloat16  g_Blo[DOUT * DIN];
__device__ int            g_count[NNODES];
__device__ int            g_off[NNODES + 1];
__device__ int            g_cursor[NNODES];
__device__ int            g_bsum[SCAN_BLK];
__device__ int            g_bpre[SCAN_BLK];
__device__ int2           g_edge_s[EDGES_MAX];

// ---------------- JAX threefry2x32, partitionable layout (key = (0,42)) ----
__device__ __forceinline__ uint32_t rotl32(uint32_t x, int r) {
    return __funnelshift_l(x, x, r);
}

__device__ __forceinline__ uint32_t threefry_bits(uint32_t idx) {
    const uint32_t ks0 = 0u;
    const uint32_t ks1 = 42u;
    const uint32_t ks2 = 0x1BD11BDAu ^ 42u;
    uint32_t x0 = 0u;
    uint32_t x1 = idx;
    x0 += ks0; x1 += ks1;
#define TFR(r) { x0 += x1; x1 = rotl32(x1, r); x1 ^= x0; }
    TFR(13) TFR(15) TFR(26) TFR(6)   x0 += ks1; x1 += ks2 + 1u;
    TFR(17) TFR(29) TFR(16) TFR(24)  x0 += ks2; x1 += ks0 + 2u;
    TFR(13) TFR(15) TFR(26) TFR(6)   x0 += ks0; x1 += ks1 + 3u;
    TFR(17) TFR(29) TFR(16) TFR(24)  x0 += ks1; x1 += ks2 + 4u;
    TFR(13) TFR(15) TFR(26) TFR(6)   x0 += ks2; x1 += ks0 + 5u;
#undef TFR
    return x0 ^ x1;
}

__device__ __forceinline__ float dropout_val(float v, uint32_t idx) {
    uint32_t m = threefry_bits(idx) >> 9;
    return (m < KEEP_THRESH) ? v * INV_KEEP : 0.0f;
}

// ---------------- kernel 0: split W into bf16 hi/lo, K-major [n][k] --------
__global__ void wsplit_kernel(const float* __restrict__ W) {
    int i = blockIdx.x * blockDim.x + threadIdx.x;
    if (i < DOUT * DIN) {
        int n = i >> 9;           // /DIN
        int k = i & (DIN - 1);
        float w = W[(size_t)k * DOUT + n];
        __nv_bfloat16 hi = __float2bfloat16(w);
        float lo = w - __bfloat162float(hi);
        g_Bhi[i] = hi;
        g_Blo[i] = __float2bfloat16(lo);
    }
}

// ---------------- kernel 1: dropout + split-bf16 wmma GEMM, double-buffered
// CTA 64x256 (full DOUT, threefry once per element). 8 warps 2(M)x4(N),
// warp tile 32x64 = 2x4 frags. C = Ah*Bh + Ah*Bl + Al*Bh (fp32 accum).
// Pipeline: ldg x(ch+1) -> MMA(ch) -> prep-store(ch+1) -> one sync.
__global__ void __launch_bounds__(256, 1) gemm_wmma_kernel(
    const float* __restrict__ x, int M)
{
    extern __shared__ __align__(128) __nv_bfloat16 smem[];

    const int tid  = threadIdx.x;
    const int wid  = tid >> 5;
    const int lane = tid & 31;
    const int wm = wid & 1;              // M offset wm*32
    const int wn = wid >> 1;             // N offset wn*64
    const int bm = blockIdx.x * BMT;

    // A-prep map: 4 threads per row, 8 k each
    const int arow = tid >> 2;                 // 0..63
    const int akof = (tid & 3) * 8;            // 0,8,16,24
    const int grow = bm + arow;
    const bool rok = (grow < M);

    wmma::fragment<wmma::accumulator, 16, 16, 16, float> c[2][4];
#pragma unroll
    for (int i = 0; i < 2; ++i)
#pragma unroll
        for (int j = 0; j < 4; ++j) wmma::fill_fragment(c[i][j], 0.0f);

    // stage pointers
    __nv_bfloat16* Ahi[2] = { smem,                     smem + BUF_SEC };
    __nv_bfloat16* Alo[2] = { smem + A_SEC,             smem + BUF_SEC + A_SEC };
    __nv_bfloat16* Bhi[2] = { smem + 2*A_SEC,           smem + BUF_SEC + 2*A_SEC };
    __nv_bfloat16* Blo[2] = { smem + 2*A_SEC + B_SEC,   smem + BUF_SEC + 2*A_SEC + B_SEC };

    // ---- prep(ch, buf): threefry+split A, load B planes ----
    auto prep = [&](int ch, int buf, const float4 va[2]) {
        // A
        float f[8];
        if (rok) {
#pragma unroll
            for (int q = 0; q < 2; ++q) {
                uint32_t base = (uint32_t)grow * DIN + (uint32_t)(ch * KC + akof + q * 4);
                f[q*4+0] = dropout_val(va[q].x, base);
                f[q*4+1] = dropout_val(va[q].y, base + 1u);
                f[q*4+2] = dropout_val(va[q].z, base + 2u);
                f[q*4+3] = dropout_val(va[q].w, base + 3u);
            }
        } else {
#pragma unroll
            for (int q = 0; q < 8; ++q) f[q] = 0.f;
        }
        __nv_bfloat16* ah = Ahi[buf] + arow * LDS_T + akof;
        __nv_bfloat16* al = Alo[buf] + arow * LDS_T + akof;
#pragma unroll
        for (int q = 0; q < 8; ++q) {
            __nv_bfloat16 hi = __float2bfloat16(f[q]);
            ah[q] = hi;
            al[q] = __float2bfloat16(f[q] - __bfloat162float(hi));
        }
        // B (L2-resident planes); 8B smem stores (72B row stride safe)
        const int k0 = ch * KC;
        const __nv_bfloat16* ph = g_Bhi + (size_t)tid * DIN + k0;
        const __nv_bfloat16* pl = g_Blo + (size_t)tid * DIN + k0;
        __nv_bfloat16* bh = Bhi[buf] + tid * LDS_T;
        __nv_bfloat16* bl = Blo[buf] + tid * LDS_T;
#pragma unroll
        for (int q = 0; q < 4; ++q) {
            uint4 vh = __ldg((const uint4*)(ph) + q);
            uint4 vl = __ldg((const uint4*)(pl) + q);
            *(uint2*)(bh + q * 8)     = make_uint2(vh.x, vh.y);
            *(uint2*)(bh + q * 8 + 4) = make_uint2(vh.z, vh.w);
            *(uint2*)(bl + q * 8)     = make_uint2(vl.x, vl.y);
            *(uint2*)(bl + q * 8 + 4) = make_uint2(vl.z, vl.w);
        }
    };

    // ---- prologue: fill stage 0 ----
    {
        float4 va[2] = { make_float4(0,0,0,0), make_float4(0,0,0,0) };
        if (rok) {
            va[0] = *(const float4*)(x + (size_t)grow * DIN + akof);
            va[1] = *(const float4*)(x + (size_t)grow * DIN + akof + 4);
        }
        prep(0, 0, va);
    }
    __syncthreads();

    for (int ch = 0; ch < NCHUNK; ++ch) {
        const int cur = ch & 1;

        // (1) issue next-chunk x loads early (DRAM latency under MMA)
        float4 va[2] = { make_float4(0,0,0,0), make_float4(0,0,0,0) };
        if (ch + 1 < NCHUNK && rok) {
            const float* xp = x + (size_t)grow * DIN + (ch + 1) * KC + akof;
            va[0] = *(const float4*)(xp);
            va[1] = *(const float4*)(xp + 4);
        }

        // (2) MMA on current stage: 2 ksteps x (2x4) x 3 products
#pragma unroll
        for (int ks = 0; ks < 2; ++ks) {
            wmma::fragment<wmma::matrix_a, 16, 16, 16, __nv_bfloat16, wmma::row_major> ah[2], al[2];
            wmma::fragment<wmma::matrix_b, 16, 16, 16, __nv_bfloat16, wmma::col_major> bh[4], bl[4];
#pragma unroll
            for (int i = 0; i < 2; ++i) {
                wmma::load_matrix_sync(ah[i], Ahi[cur] + (wm*32 + i*16) * LDS_T + ks*16, LDS_T);
                wmma::load_matrix_sync(al[i], Alo[cur] + (wm*32 + i*16) * LDS_T + ks*16, LDS_T);
            }
#pragma unroll
            for (int j = 0; j < 4; ++j) {
                wmma::load_matrix_sync(bh[j], Bhi[cur] + (wn*64 + j*16) * LDS_T + ks*16, LDS_T);
                wmma::load_matrix_sync(bl[j], Blo[cur] + (wn*64 + j*16) * LDS_T + ks*16, LDS_T);
            }
#pragma unroll
            for (int i = 0; i < 2; ++i)
#pragma unroll
                for (int j = 0; j < 4; ++j) {
                    wmma::mma_sync(c[i][j], ah[i], bh[j], c[i][j]);
                    wmma::mma_sync(c[i][j], ah[i], bl[j], c[i][j]);
                    wmma::mma_sync(c[i][j], al[i], bh[j], c[i][j]);
                }
        }

        // (3) prep next stage (ALU overlaps tensor drain)
        if (ch + 1 < NCHUNK) prep(ch + 1, cur ^ 1, va);

        // (4) single barrier per chunk
        __syncthreads();
    }

    // ---- epilogue: per-warp 16x16 fp32 patch (reuse smem) -> fp16 g_h ----
    float* patch = (float*)smem + wid * 256;
    const int prow = lane >> 1;                 // 0..15
    const int pcol = (lane & 1) * 8;            // 0 / 8

#pragma unroll
    for (int i = 0; i < 2; ++i)
#pragma unroll
        for (int j = 0; j < 4; ++j) {
            wmma::store_matrix_sync(patch, c[i][j], 16, wmma::mem_row_major);
            __syncwarp();
            int orow = bm + wm*32 + i*16 + prow;
            if (orow < M) {
                const float* pr = patch + prow * 16 + pcol;
                __half2 p0 = __floats2half2_rn(pr[0], pr[1]);
                __half2 p1 = __floats2half2_rn(pr[2], pr[3]);
                __half2 p2 = __floats2half2_rn(pr[4], pr[5]);
                __half2 p3 = __floats2half2_rn(pr[6], pr[7]);
                uint4 u;
                u.x = *(uint32_t*)&p0; u.y = *(uint32_t*)&p1;
                u.z = *(uint32_t*)&p2; u.w = *(uint32_t*)&p3;
                *(uint4*)(g_h + (size_t)orow * DOUT + wn*64 + j*16 + pcol) = u;
            }
            __syncwarp();
        }
}

// ---------------- CSR build ----------------
__global__ void zero_count_kernel() {
    int i = blockIdx.x * blockDim.x + threadIdx.x;
    if (i < NNODES) g_count[i] = 0;
}

__global__ void hist_kernel(const int* __restrict__ edst, int E) {
    int e = blockIdx.x * blockDim.x + threadIdx.x;
    if (e < E) atomicAdd(&g_count[edst[e]], 1);
}

__global__ __launch_bounds__(1024) void scanA_kernel() {
    __shared__ int wsum[32];
    const int t = threadIdx.x, b = blockIdx.x;
    const int lane = t & 31, wid = t >> 5;
    int i = b * 1024 + t;
    int v = (i < NNODES) ? g_count[i] : 0;
    int s = v;
#pragma unroll
    for (int off = 16; off > 0; off >>= 1)
        s += __shfl_down_sync(0xffffffffu, s, off);
    if (lane == 0) wsum[wid] = s;
    __syncthreads();
    if (wid == 0) {
        int r = wsum[lane];
#pragma unroll
        for (int off = 16; off > 0; off >>= 1)
            r += __shfl_down_sync(0xffffffffu, r, off);
        if (lane == 0) g_bsum[b] = r;
    }
}

__global__ __launch_bounds__(128) void scanB_kernel() {
    __shared__ int sh[128];
    const int t = threadIdx.x;
    int v = (t < SCAN_BLK) ? g_bsum[t] : 0;
    sh[t] = v;
    __syncthreads();
#pragma unroll
    for (int off = 1; off < 128; off <<= 1) {
        int y = (t >= off) ? sh[t - off] : 0;
        __syncthreads();
        sh[t] += y;
        __syncthreads();
    }
    if (t < SCAN_BLK) g_bpre[t] = sh[t] - v;
    if (t == 127) g_off[NNODES] = sh[127];
}

__global__ __launch_bounds__(1024) void scanC_kernel() {
    __shared__ int wsum[32];
    const int t = threadIdx.x, b = blockIdx.x;
    const int lane = t & 31, wid = t >> 5;
    int i = b * 1024 + t;
    int v = (i < NNODES) ? g_count[i] : 0;
    int xv = v;
#pragma unroll
    for (int off = 1; off < 32; off <<= 1) {
        int y = __shfl_up_sync(0xffffffffu, xv, off);
        if (lane >= off) xv += y;
    }
    if (lane == 31) wsum[wid] = xv;
    __syncthreads();
    if (wid == 0) {
        int s0 = wsum[lane];
        int s = s0;
#pragma unroll
        for (int off = 1; off < 32; off <<= 1) {
            int y = __shfl_up_sync(0xffffffffu, s, off);
            if (lane >= off) s += y;
        }
        wsum[lane] = s - s0;
    }
    __syncthreads();
    if (i < NNODES) {
        int excl = (xv - v) + wsum[wid] + g_bpre[b];
        g_off[i]    = excl;
        g_cursor[i] = excl;
    }
}

__global__ void reorder_kernel(const int* __restrict__ esrc,
                               const int* __restrict__ edst,
                               const float* __restrict__ ew, int E)
{
    int e = blockIdx.x * blockDim.x + threadIdx.x;
    if (e < E) {
        int d = edst[e];
        int pos = atomicAdd(&g_cursor[d], 1);
        g_edge_s[pos] = make_int2(esrc[e], __float_as_int(ew[e]));
    }
}

// ---------------- aggregation: 1 warp per dst node, fp16 gather ------------
__global__ __launch_bounds__(256) void agg_kernel(float* __restrict__ out, int N)
{
    int node = blockIdx.x * 8 + (threadIdx.x >> 5);
    int lane = threadIdx.x & 31;
    if (node >= N) return;

    int beg = g_off[node];
    int end = g_off[node + 1];

    float a[8] = {0.f, 0.f, 0.f, 0.f, 0.f, 0.f, 0.f, 0.f};

    for (int j = beg; j < end; j += 32) {
        int n = min(32, end - j);
        int2 e = (lane < n) ? __ldg(&g_edge_s[j + lane]) : make_int2(0, 0);
        for (int t = 0; t < n; ++t) {
            int   s = __shfl_sync(0xffffffffu, e.x, t);
            float w = __int_as_float(__shfl_sync(0xffffffffu, e.y, t));
            const uint4* hp = (const uint4*)(g_h + (size_t)s * DOUT);
            uint4 u = __ldg(hp + lane);
            float2 f0 = __half22float2(*(__half2*)&u.x);
            float2 f1 = __half22float2(*(__half2*)&u.y);
            float2 f2 = __half22float2(*(__half2*)&u.z);
            float2 f3 = __half22float2(*(__half2*)&u.w);
            a[0] = fmaf(w, f0.x, a[0]); a[1] = fmaf(w, f0.y, a[1]);
            a[2] = fmaf(w, f1.x, a[2]); a[3] = fmaf(w, f1.y, a[3]);
            a[4] = fmaf(w, f2.x, a[4]); a[5] = fmaf(w, f2.y, a[5]);
            a[6] = fmaf(w, f3.x, a[6]); a[7] = fmaf(w, f3.y, a[7]);
        }
    }

#pragma unroll
    for (int i = 0; i < 8; ++i) a[i] = fmaxf(a[i], 0.f);

    float* op = out + (size_t)node * DOUT + lane * 8;
    *(float4*)(op)     = make_float4(a[0], a[1], a[2], a[3]);
    *(float4*)(op + 4) = make_float4(a[4], a[5], a[6], a[7]);
}

// ---------------- launch ----------------
extern "C" void kernel_launch(void* const* d_in, const int* in_sizes, int n_in,
                              void* d_out, int out_size)
{
    const float* x    = (const float*)d_in[0];
    const float* W    = (const float*)d_in[1];
    const int*   esrc = (const int*)d_in[2];
    const int*   edst = (const int*)d_in[3];
    const float* ew   = (const float*)d_in[4];
    float*       out  = (float*)d_out;

    const int M = in_sizes[0] / DIN;   // 100000
    const int E = in_sizes[2];         // 3200000
    const int smem_bytes = SMEM_ELEMS * 2;   // 92160

    cudaFuncSetAttribute(gemm_wmma_kernel,
                         cudaFuncAttributeMaxDynamicSharedMemorySize, smem_bytes);

    // 1) W split + double-buffered wmma GEMM (h in fp16)
    wsplit_kernel<<<(DOUT * DIN + 255) / 256, 256>>>(W);
    gemm_wmma_kernel<<<(M + BMT - 1) / BMT, 256, smem_bytes>>>(x, M);

    // 2) CSR build (dst-major edge ordering)
    zero_count_kernel<<<(NNODES + 255) / 256, 256>>>();
    hist_kernel<<<(E + 255) / 256, 256>>>(edst, E);
    scanA_kernel<<<SCAN_BLK, 1024>>>();
    scanB_kernel<<<1, 128>>>();
    scanC_kernel<<<SCAN_BLK, 1024>>>();
    reorder_kernel<<<(E + 255) / 256, 256>>>(esrc, edst, ew, E);

    // 3) aggregate + relu, one warp per dst node, plain stores
    agg_kernel<<<(M + 7) / 8, 256>>>(out, M);
}

// round 12
// speedup vs baseline: 1.2195x; 1.2195x over previous
#include <cuda_runtime.h>
#include <cuda_fp16.h>
#include <cuda_bf16.h>
#include <mma.h>
#include <cstdint>

using namespace nvcuda;

// ---------------- problem constants ----------------
#define NNODES   100000
#define DIN      512
#define DOUT     256
#define EDGES_MAX 3200000
#define KEEP_THRESH 7549747u          // 0.9f == 7549747 * 2^-23 exactly
#define INV_KEEP (1.0f/0.9f)
#define SCAN_BLK  98

// GEMM tiling (wmma HMMA path, compute_103-safe) — R10 proven config
#define BMT 64
#define BNT 256
#define KC  32
#define NCHUNK (DIN / KC)             // 16
#define LDS_T 36                      // 72B row stride; 8B stores aligned, frag rows 16x

// scratch
__device__ __half         g_h[(size_t)NNODES * DOUT];   // 51.2 MB fp16
__device__ __nv_bfloat16  g_Bhi[DOUT * DIN];            // W split, K-major [n][k]
__device__ __nv_bfloat16  g_Blo[DOUT * DIN];
__device__ int            g_count[NNODES];
__device__ int            g_off[NNODES + 1];
__device__ int            g_cursor[NNODES];
__device__ int            g_bsum[SCAN_BLK];
__device__ int            g_bpre[SCAN_BLK];
__device__ int2           g_edge_s[EDGES_MAX];

// ---------------- JAX threefry2x32, partitionable layout (key = (0,42)) ----
__device__ __forceinline__ uint32_t rotl32(uint32_t x, int r) {
    return __funnelshift_l(x, x, r);
}

__device__ __forceinline__ uint32_t threefry_bits(uint32_t idx) {
    const uint32_t ks0 = 0u;
    const uint32_t ks1 = 42u;
    const uint32_t ks2 = 0x1BD11BDAu ^ 42u;
    uint32_t x0 = 0u;
    uint32_t x1 = idx;
    x0 += ks0; x1 += ks1;
#define TFR(r) { x0 += x1; x1 = rotl32(x1, r); x1 ^= x0; }
    TFR(13) TFR(15) TFR(26) TFR(6)   x0 += ks1; x1 += ks2 + 1u;
    TFR(17) TFR(29) TFR(16) TFR(24)  x0 += ks2; x1 += ks0 + 2u;
    TFR(13) TFR(15) TFR(26) TFR(6)   x0 += ks0; x1 += ks1 + 3u;
    TFR(17) TFR(29) TFR(16) TFR(24)  x0 += ks1; x1 += ks2 + 4u;
    TFR(13) TFR(15) TFR(26) TFR(6)   x0 += ks2; x1 += ks0 + 5u;
#undef TFR
    return x0 ^ x1;
}

__device__ __forceinline__ float dropout_val(float v, uint32_t idx) {
    uint32_t m = threefry_bits(idx) >> 9;
    return (m < KEEP_THRESH) ? v * INV_KEEP : 0.0f;
}

// ---------------- kernel 0: split W into bf16 hi/lo, K-major [n][k] --------
__global__ void wsplit_kernel(const float* __restrict__ W) {
    int i = blockIdx.x * blockDim.x + threadIdx.x;
    if (i < DOUT * DIN) {
        int n = i >> 9;           // /DIN
        int k = i & (DIN - 1);
        float w = W[(size_t)k * DOUT + n];
        __nv_bfloat16 hi = __float2bfloat16(w);
        float lo = w - __bfloat162float(hi);
        g_Bhi[i] = hi;
        g_Blo[i] = __float2bfloat16(lo);
    }
}

// ---------------- kernel 1: dropout + split-bf16 wmma GEMM -----------------
// R10 structure (single-buffer, static smem) + register prefetch of next x.
// CTA 64x256, 8 warps 2(M)x4(N), warp tile 32x64. C = Ah*Bh + Ah*Bl + Al*Bh.
__global__ void __launch_bounds__(256) gemm_wmma_kernel(
    const float* __restrict__ x, int M)
{
    __shared__ __align__(32) __nv_bfloat16 Ahi[BMT][LDS_T];
    __shared__ __align__(32) __nv_bfloat16 Alo[BMT][LDS_T];
    __shared__ __align__(32) __nv_bfloat16 Bhi[BNT][LDS_T];   // [n][k]
    __shared__ __align__(32) __nv_bfloat16 Blo[BNT][LDS_T];

    const int tid  = threadIdx.x;
    const int wid  = tid >> 5;
    const int lane = tid & 31;
    const int wm = wid & 1;              // M offset wm*32
    const int wn = wid >> 1;             // N offset wn*64
    const int bm = blockIdx.x * BMT;

    const int arow = tid >> 2;                 // 0..63
    const int akof = (tid & 3) * 8;            // 0,8,16,24
    const int grow = bm + arow;
    const bool rok = (grow < M);

    wmma::fragment<wmma::accumulator, 16, 16, 16, float> c[2][4];
#pragma unroll
    for (int i = 0; i < 2; ++i)
#pragma unroll
        for (int j = 0; j < 4; ++j) wmma::fill_fragment(c[i][j], 0.0f);

    // prologue: load x for chunk 0
    float4 va0 = make_float4(0,0,0,0), va1 = make_float4(0,0,0,0);
    if (rok) {
        va0 = *(const float4*)(x + (size_t)grow * DIN + akof);
        va1 = *(const float4*)(x + (size_t)grow * DIN + akof + 4);
    }

    for (int ch = 0; ch < NCHUNK; ++ch) {
        const int k0 = ch * KC;

        // ---- A: dropout + hi/lo split from prefetched registers ----
        {
            float f[8];
            if (rok) {
                uint32_t base = (uint32_t)grow * DIN + (uint32_t)(k0 + akof);
                f[0] = dropout_val(va0.x, base);
                f[1] = dropout_val(va0.y, base + 1u);
                f[2] = dropout_val(va0.z, base + 2u);
                f[3] = dropout_val(va0.w, base + 3u);
                f[4] = dropout_val(va1.x, base + 4u);
                f[5] = dropout_val(va1.y, base + 5u);
                f[6] = dropout_val(va1.z, base + 6u);
                f[7] = dropout_val(va1.w, base + 7u);
            } else {
#pragma unroll
                for (int q = 0; q < 8; ++q) f[q] = 0.f;
            }
#pragma unroll
            for (int q = 0; q < 8; ++q) {
                __nv_bfloat16 hi = __float2bfloat16(f[q]);
                Ahi[arow][akof + q] = hi;
                Alo[arow][akof + q] = __float2bfloat16(f[q] - __bfloat162float(hi));
            }
        }

        // ---- B: load pre-split planes (L2-resident); 8B smem stores ----
        {
            const __nv_bfloat16* ph = g_Bhi + (size_t)tid * DIN + k0;
            const __nv_bfloat16* pl = g_Blo + (size_t)tid * DIN + k0;
#pragma unroll
            for (int q = 0; q < 4; ++q) {
                uint4 vh = __ldg((const uint4*)(ph) + q);
                uint4 vl = __ldg((const uint4*)(pl) + q);
                *(uint2*)&Bhi[tid][q * 8]     = make_uint2(vh.x, vh.y);
                *(uint2*)&Bhi[tid][q * 8 + 4] = make_uint2(vh.z, vh.w);
                *(uint2*)&Blo[tid][q * 8]     = make_uint2(vl.x, vl.y);
                *(uint2*)&Blo[tid][q * 8 + 4] = make_uint2(vl.z, vl.w);
            }
        }
        __syncthreads();

        // ---- prefetch next chunk's x (DRAM latency drains under MMA) ----
        if (ch + 1 < NCHUNK && rok) {
            const float* xp = x + (size_t)grow * DIN + (ch + 1) * KC + akof;
            va0 = *(const float4*)(xp);
            va1 = *(const float4*)(xp + 4);
        }

        // ---- MMA: 2 ksteps x (2x4 tiles) x 3 products ----
#pragma unroll
        for (int ks = 0; ks < 2; ++ks) {
            wmma::fragment<wmma::matrix_a, 16, 16, 16, __nv_bfloat16, wmma::row_major> ah[2], al[2];
            wmma::fragment<wmma::matrix_b, 16, 16, 16, __nv_bfloat16, wmma::col_major> bh[4], bl[4];
#pragma unroll
            for (int i = 0; i < 2; ++i) {
                wmma::load_matrix_sync(ah[i], &Ahi[wm*32 + i*16][ks*16], LDS_T);
                wmma::load_matrix_sync(al[i], &Alo[wm*32 + i*16][ks*16], LDS_T);
            }
#pragma unroll
            for (int j = 0; j < 4; ++j) {
                wmma::load_matrix_sync(bh[j], &Bhi[wn*64 + j*16][ks*16], LDS_T);
                wmma::load_matrix_sync(bl[j], &Blo[wn*64 + j*16][ks*16], LDS_T);
            }
#pragma unroll
            for (int i = 0; i < 2; ++i)
#pragma unroll
                for (int j = 0; j < 4; ++j) {
                    wmma::mma_sync(c[i][j], ah[i], bh[j], c[i][j]);
                    wmma::mma_sync(c[i][j], ah[i], bl[j], c[i][j]);
                    wmma::mma_sync(c[i][j], al[i], bh[j], c[i][j]);
                }
        }
        __syncthreads();
    }

    // ---- epilogue: per-warp 16x16 patch (in Bhi region) -> fp16 g_h ----
    float* patch = (float*)&Bhi[0][0] + wid * 256;
    const int prow = lane >> 1;
    const int pcol = (lane & 1) * 8;

#pragma unroll
    for (int i = 0; i < 2; ++i)
#pragma unroll
        for (int j = 0; j < 4; ++j) {
            wmma::store_matrix_sync(patch, c[i][j], 16, wmma::mem_row_major);
            __syncwarp();
            int orow = bm + wm*32 + i*16 + prow;
            if (orow < M) {
                const float* pr = patch + prow * 16 + pcol;
                __half2 p0 = __floats2half2_rn(pr[0], pr[1]);
                __half2 p1 = __floats2half2_rn(pr[2], pr[3]);
                __half2 p2 = __floats2half2_rn(pr[4], pr[5]);
                __half2 p3 = __floats2half2_rn(pr[6], pr[7]);
                uint4 u;
                u.x = *(uint32_t*)&p0; u.y = *(uint32_t*)&p1;
                u.z = *(uint32_t*)&p2; u.w = *(uint32_t*)&p3;
                *(uint4*)(g_h + (size_t)orow * DOUT + wn*64 + j*16 + pcol) = u;
            }
            __syncwarp();
        }
}

// ---------------- CSR build ----------------
__global__ void zero_count_kernel() {
    int i = blockIdx.x * blockDim.x + threadIdx.x;
    if (i < NNODES) g_count[i] = 0;
}

__global__ void hist_kernel(const int* __restrict__ edst, int E) {
    int e = blockIdx.x * blockDim.x + threadIdx.x;
    if (e < E) atomicAdd(&g_count[edst[e]], 1);
}

__global__ __launch_bounds__(1024) void scanA_kernel() {
    __shared__ int wsum[32];
    const int t = threadIdx.x, b = blockIdx.x;
    const int lane = t & 31, wid = t >> 5;
    int i = b * 1024 + t;
    int v = (i < NNODES) ? g_count[i] : 0;
    int s = v;
#pragma unroll
    for (int off = 16; off > 0; off >>= 1)
        s += __shfl_down_sync(0xffffffffu, s, off);
    if (lane == 0) wsum[wid] = s;
    __syncthreads();
    if (wid == 0) {
        int r = wsum[lane];
#pragma unroll
        for (int off = 16; off > 0; off >>= 1)
            r += __shfl_down_sync(0xffffffffu, r, off);
        if (lane == 0) g_bsum[b] = r;
    }
}

__global__ __launch_bounds__(128) void scanB_kernel() {
    __shared__ int sh[128];
    const int t = threadIdx.x;
    int v = (t < SCAN_BLK) ? g_bsum[t] : 0;
    sh[t] = v;
    __syncthreads();
#pragma unroll
    for (int off = 1; off < 128; off <<= 1) {
        int y = (t >= off) ? sh[t - off] : 0;
        __syncthreads();
        sh[t] += y;
        __syncthreads();
    }
    if (t < SCAN_BLK) g_bpre[t] = sh[t] - v;
    if (t == 127) g_off[NNODES] = sh[127];
}

__global__ __launch_bounds__(1024) void scanC_kernel() {
    __shared__ int wsum[32];
    const int t = threadIdx.x, b = blockIdx.x;
    const int lane = t & 31, wid = t >> 5;
    int i = b * 1024 + t;
    int v = (i < NNODES) ? g_count[i] : 0;
    int xv = v;
#pragma unroll
    for (int off = 1; off < 32; off <<= 1) {
        int y = __shfl_up_sync(0xffffffffu, xv, off);
        if (lane >= off) xv += y;
    }
    if (lane == 31) wsum[wid] = xv;
    __syncthreads();
    if (wid == 0) {
        int s0 = wsum[lane];
        int s = s0;
#pragma unroll
        for (int off = 1; off < 32; off <<= 1) {
            int y = __shfl_up_sync(0xffffffffu, s, off);
            if (lane >= off) s += y;
        }
        wsum[lane] = s - s0;
    }
    __syncthreads();
    if (i < NNODES) {
        int excl = (xv - v) + wsum[wid] + g_bpre[b];
        g_off[i]    = excl;
        g_cursor[i] = excl;
    }
}

__global__ void reorder_kernel(const int* __restrict__ esrc,
                               const int* __restrict__ edst,
                               const float* __restrict__ ew, int E)
{
    int e = blockIdx.x * blockDim.x + threadIdx.x;
    if (e < E) {
        int d = edst[e];
        int pos = atomicAdd(&g_cursor[d], 1);
        g_edge_s[pos] = make_int2(esrc[e], __float_as_int(ew[e]));
    }
}

// ---------------- aggregation: 1 warp per dst node, fp16 gather ------------
__global__ __launch_bounds__(256) void agg_kernel(float* __restrict__ out, int N)
{
    int node = blockIdx.x * 8 + (threadIdx.x >> 5);
    int lane = threadIdx.x & 31;
    if (node >= N) return;

    int beg = g_off[node];
    int end = g_off[node + 1];

    float a[8] = {0.f, 0.f, 0.f, 0.f, 0.f, 0.f, 0.f, 0.f};

    for (int j = beg; j < end; j += 32) {
        int n = min(32, end - j);
        int2 e = (lane < n) ? __ldg(&g_edge_s[j + lane]) : make_int2(0, 0);
        for (int t = 0; t < n; ++t) {
            int   s = __shfl_sync(0xffffffffu, e.x, t);
            float w = __int_as_float(__shfl_sync(0xffffffffu, e.y, t));
            const uint4* hp = (const uint4*)(g_h + (size_t)s * DOUT);
            uint4 u = __ldg(hp + lane);
            float2 f0 = __half22float2(*(__half2*)&u.x);
            float2 f1 = __half22float2(*(__half2*)&u.y);
            float2 f2 = __half22float2(*(__half2*)&u.z);
            float2 f3 = __half22float2(*(__half2*)&u.w);
            a[0] = fmaf(w, f0.x, a[0]); a[1] = fmaf(w, f0.y, a[1]);
            a[2] = fmaf(w, f1.x, a[2]); a[3] = fmaf(w, f1.y, a[3]);
            a[4] = fmaf(w, f2.x, a[4]); a[5] = fmaf(w, f2.y, a[5]);
            a[6] = fmaf(w, f3.x, a[6]); a[7] = fmaf(w, f3.y, a[7]);
        }
    }

#pragma unroll
    for (int i = 0; i < 8; ++i) a[i] = fmaxf(a[i], 0.f);

    float* op = out + (size_t)node * DOUT + lane * 8;
    *(float4*)(op)     = make_float4(a[0], a[1], a[2], a[3]);
    *(float4*)(op + 4) = make_float4(a[4], a[5], a[6], a[7]);
}

// ---------------- launch: fork-join graph (GEMM || CSR build) --------------
extern "C" void kernel_launch(void* const* d_in, const int* in_sizes, int n_in,
                              void* d_out, int out_size)
{
    const float* x    = (const float*)d_in[0];
    const float* W    = (const float*)d_in[1];
    const int*   esrc = (const int*)d_in[2];
    const int*   edst = (const int*)d_in[3];
    const float* ew   = (const float*)d_in[4];
    float*       out  = (float*)d_out;

    const int M = in_sizes[0] / DIN;   // 100000
    const int E = in_sizes[2];         // 3200000

    // one-time side stream + events (created on first, non-captured call;
    // no device memory allocated)
    static cudaStream_t s2 = nullptr;
    static cudaEvent_t  evF = nullptr, evJ = nullptr;
    if (!s2) {
        cudaStreamCreateWithFlags(&s2, cudaStreamNonBlocking);
        cudaEventCreateWithFlags(&evF, cudaEventDisableTiming);
        cudaEventCreateWithFlags(&evJ, cudaEventDisableTiming);
    }

    // fork: side stream joins the captured graph
    cudaEventRecord(evF, 0);
    cudaStreamWaitEvent(s2, evF, 0);

    // branch A (main stream): W split + GEMM (tensor/ALU-bound)
    wsplit_kernel<<<(DOUT * DIN + 255) / 256, 256>>>(W);
    gemm_wmma_kernel<<<(M + BMT - 1) / BMT, 256>>>(x, M);

    // branch B (side stream): CSR build (LTS/atomic-bound)
    zero_count_kernel<<<(NNODES + 255) / 256, 256, 0, s2>>>();
    hist_kernel<<<(E + 255) / 256, 256, 0, s2>>>(edst, E);
    scanA_kernel<<<SCAN_BLK, 1024, 0, s2>>>();
    scanB_kernel<<<1, 128, 0, s2>>>();
    scanC_kernel<<<SCAN_BLK, 1024, 0, s2>>>();
    reorder_kernel<<<(E + 255) / 256, 256, 0, s2>>>(esrc, edst, ew, E);

    // join: agg needs both h and the CSR
    cudaEventRecord(evJ, s2);
    cudaStreamWaitEvent(0, evJ, 0);

    agg_kernel<<<(M + 7) / 8, 256>>>(out, M);
}

// round 13
// speedup vs baseline: 1.4310x; 1.1735x over previous
#include <cuda_runtime.h>
#include <cuda_fp16.h>
#include <cuda_bf16.h>
#include <mma.h>
#include <cstdint>

using namespace nvcuda;

// ---------------- problem constants ----------------
#define NNODES   100000
#define DIN      512
#define DOUT     256
#define EDGES_MAX 3200000
#define KEEP_THRESH 7549747u          // 0.9f == 7549747 * 2^-23 exactly
#define INV_KEEP (1.0f/0.9f)
#define SCAN_BLK  98

// GEMM tiling (wmma HMMA path, compute_103-safe)
#define BMT 64
#define BNT 256
#define KC  32
#define NCHUNK (DIN / KC)             // 16
#define LDS_T 36                      // 72B row stride; 8B stores aligned, frag rows 16x

// scratch
__device__ __half         g_h[(size_t)NNODES * DOUT];   // 51.2 MB fp16
__device__ __nv_bfloat16  g_Bhi[DOUT * DIN];            // W split, K-major [n][k]
__device__ __nv_bfloat16  g_Blo[DOUT * DIN];
__device__ int            g_count[NNODES];
__device__ int            g_off[NNODES + 1];
__device__ int            g_cursor[NNODES];
__device__ int            g_bsum[SCAN_BLK];
__device__ int            g_bpre[SCAN_BLK];
__device__ int2           g_edge_s[EDGES_MAX];

// ---------------- JAX threefry2x32, partitionable layout (key = (0,42)) ----
__device__ __forceinline__ uint32_t rotl32(uint32_t x, int r) {
    return __funnelshift_l(x, x, r);
}

__device__ __forceinline__ uint32_t threefry_bits(uint32_t idx) {
    const uint32_t ks0 = 0u;
    const uint32_t ks1 = 42u;
    const uint32_t ks2 = 0x1BD11BDAu ^ 42u;
    uint32_t x0 = 0u;
    uint32_t x1 = idx;
    x0 += ks0; x1 += ks1;
#define TFR(r) { x0 += x1; x1 = rotl32(x1, r); x1 ^= x0; }
    TFR(13) TFR(15) TFR(26) TFR(6)   x0 += ks1; x1 += ks2 + 1u;
    TFR(17) TFR(29) TFR(16) TFR(24)  x0 += ks2; x1 += ks0 + 2u;
    TFR(13) TFR(15) TFR(26) TFR(6)   x0 += ks0; x1 += ks1 + 3u;
    TFR(17) TFR(29) TFR(16) TFR(24)  x0 += ks1; x1 += ks2 + 4u;
    TFR(13) TFR(15) TFR(26) TFR(6)   x0 += ks2; x1 += ks0 + 5u;
#undef TFR
    return x0 ^ x1;
}

__device__ __forceinline__ float dropout_val(float v, uint32_t idx) {
    uint32_t m = threefry_bits(idx) >> 9;
    return (m < KEEP_THRESH) ? v * INV_KEEP : 0.0f;
}

// ---------------- kernel 0: split W into bf16 hi/lo, K-major [n][k] --------
__global__ void wsplit_kernel(const float* __restrict__ W) {
    int i = blockIdx.x * blockDim.x + threadIdx.x;
    if (i < DOUT * DIN) {
        int n = i >> 9;           // /DIN
        int k = i & (DIN - 1);
        float w = W[(size_t)k * DOUT + n];
        __nv_bfloat16 hi = __float2bfloat16(w);
        float lo = w - __bfloat162float(hi);
        g_Bhi[i] = hi;
        g_Blo[i] = __float2bfloat16(lo);
    }
}

// ---------------- kernel 1: dropout + split-bf16 wmma GEMM -----------------
// occ=2 CTAs/SM: cross-CTA overlap of prep (ALU) with MMA (tensor).
// CTA 64x256, 8 warps 2(M)x4(N), warp tile 32x64. C = Ah*Bh + Ah*Bl + Al*Bh.
__global__ void __launch_bounds__(256, 2) gemm_wmma_kernel(
    const float* __restrict__ x, int M)
{
    __shared__ __align__(32) __nv_bfloat16 Ahi[BMT][LDS_T];
    __shared__ __align__(32) __nv_bfloat16 Alo[BMT][LDS_T];
    __shared__ __align__(32) __nv_bfloat16 Bhi[BNT][LDS_T];   // [n][k]
    __shared__ __align__(32) __nv_bfloat16 Blo[BNT][LDS_T];

    const int tid  = threadIdx.x;
    const int wid  = tid >> 5;
    const int lane = tid & 31;
    const int wm = wid & 1;              // M offset wm*32
    const int wn = wid >> 1;             // N offset wn*64
    const int bm = blockIdx.x * BMT;

    const int arow = tid >> 2;                 // 0..63
    const int akof = (tid & 3) * 8;            // 0,8,16,24
    const int grow = bm + arow;
    const bool rok = (grow < M);

    wmma::fragment<wmma::accumulator, 16, 16, 16, float> c[2][4];
#pragma unroll
    for (int i = 0; i < 2; ++i)
#pragma unroll
        for (int j = 0; j < 4; ++j) wmma::fill_fragment(c[i][j], 0.0f);

    for (int ch = 0; ch < NCHUNK; ++ch) {
        const int k0 = ch * KC;

        // ---- A: dropout + hi/lo split ----
        {
            float f[8];
            if (rok) {
                const float* xp = x + (size_t)grow * DIN + k0 + akof;
                float4 v0 = *(const float4*)(xp);
                float4 v1 = *(const float4*)(xp + 4);
                uint32_t base = (uint32_t)grow * DIN + (uint32_t)(k0 + akof);
                f[0] = dropout_val(v0.x, base);
                f[1] = dropout_val(v0.y, base + 1u);
                f[2] = dropout_val(v0.z, base + 2u);
                f[3] = dropout_val(v0.w, base + 3u);
                f[4] = dropout_val(v1.x, base + 4u);
                f[5] = dropout_val(v1.y, base + 5u);
                f[6] = dropout_val(v1.z, base + 6u);
                f[7] = dropout_val(v1.w, base + 7u);
            } else {
#pragma unroll
                for (int q = 0; q < 8; ++q) f[q] = 0.f;
            }
#pragma unroll
            for (int q = 0; q < 8; ++q) {
                __nv_bfloat16 hi = __float2bfloat16(f[q]);
                Ahi[arow][akof + q] = hi;
                Alo[arow][akof + q] = __float2bfloat16(f[q] - __bfloat162float(hi));
            }
        }

        // ---- B: load pre-split planes (L2-resident); 8B smem stores ----
        {
            const __nv_bfloat16* ph = g_Bhi + (size_t)tid * DIN + k0;
            const __nv_bfloat16* pl = g_Blo + (size_t)tid * DIN + k0;
#pragma unroll
            for (int q = 0; q < 4; ++q) {
                uint4 vh = __ldg((const uint4*)(ph) + q);
                uint4 vl = __ldg((const uint4*)(pl) + q);
                *(uint2*)&Bhi[tid][q * 8]     = make_uint2(vh.x, vh.y);
                *(uint2*)&Bhi[tid][q * 8 + 4] = make_uint2(vh.z, vh.w);
                *(uint2*)&Blo[tid][q * 8]     = make_uint2(vl.x, vl.y);
                *(uint2*)&Blo[tid][q * 8 + 4] = make_uint2(vl.z, vl.w);
            }
        }
        __syncthreads();

        // ---- MMA: 2 ksteps x (2x4 tiles) x 3 products ----
#pragma unroll
        for (int ks = 0; ks < 2; ++ks) {
            wmma::fragment<wmma::matrix_a, 16, 16, 16, __nv_bfloat16, wmma::row_major> ah[2], al[2];
            wmma::fragment<wmma::matrix_b, 16, 16, 16, __nv_bfloat16, wmma::col_major> bh[4], bl[4];
#pragma unroll
            for (int i = 0; i < 2; ++i) {
                wmma::load_matrix_sync(ah[i], &Ahi[wm*32 + i*16][ks*16], LDS_T);
                wmma::load_matrix_sync(al[i], &Alo[wm*32 + i*16][ks*16], LDS_T);
            }
#pragma unroll
            for (int j = 0; j < 4; ++j) {
                wmma::load_matrix_sync(bh[j], &Bhi[wn*64 + j*16][ks*16], LDS_T);
                wmma::load_matrix_sync(bl[j], &Blo[wn*64 + j*16][ks*16], LDS_T);
            }
#pragma unroll
            for (int i = 0; i < 2; ++i)
#pragma unroll
                for (int j = 0; j < 4; ++j) {
                    wmma::mma_sync(c[i][j], ah[i], bh[j], c[i][j]);
                    wmma::mma_sync(c[i][j], ah[i], bl[j], c[i][j]);
                    wmma::mma_sync(c[i][j], al[i], bh[j], c[i][j]);
                }
        }
        __syncthreads();
    }

    // ---- epilogue: per-warp 16x16 patch (in Bhi region) -> fp16 g_h ----
    float* patch = (float*)&Bhi[0][0] + wid * 256;
    const int prow = lane >> 1;
    const int pcol = (lane & 1) * 8;

#pragma unroll
    for (int i = 0; i < 2; ++i)
#pragma unroll
        for (int j = 0; j < 4; ++j) {
            wmma::store_matrix_sync(patch, c[i][j], 16, wmma::mem_row_major);
            __syncwarp();
            int orow = bm + wm*32 + i*16 + prow;
            if (orow < M) {
                const float* pr = patch + prow * 16 + pcol;
                __half2 p0 = __floats2half2_rn(pr[0], pr[1]);
                __half2 p1 = __floats2half2_rn(pr[2], pr[3]);
                __half2 p2 = __floats2half2_rn(pr[4], pr[5]);
                __half2 p3 = __floats2half2_rn(pr[6], pr[7]);
                uint4 u;
                u.x = *(uint32_t*)&p0; u.y = *(uint32_t*)&p1;
                u.z = *(uint32_t*)&p2; u.w = *(uint32_t*)&p3;
                *(uint4*)(g_h + (size_t)orow * DOUT + wn*64 + j*16 + pcol) = u;
            }
            __syncwarp();
        }
}

// ---------------- CSR build ----------------
__global__ void zero_count_kernel() {
    int i = blockIdx.x * blockDim.x + threadIdx.x;
    if (i < NNODES) g_count[i] = 0;
}

__global__ void hist_kernel(const int* __restrict__ edst, int E) {
    int e = blockIdx.x * blockDim.x + threadIdx.x;
    if (e < E) atomicAdd(&g_count[edst[e]], 1);
}

__global__ __launch_bounds__(1024) void scanA_kernel() {
    __shared__ int wsum[32];
    const int t = threadIdx.x, b = blockIdx.x;
    const int lane = t & 31, wid = t >> 5;
    int i = b * 1024 + t;
    int v = (i < NNODES) ? g_count[i] : 0;
    int s = v;
#pragma unroll
    for (int off = 16; off > 0; off >>= 1)
        s += __shfl_down_sync(0xffffffffu, s, off);
    if (lane == 0) wsum[wid] = s;
    __syncthreads();
    if (wid == 0) {
        int r = wsum[lane];
#pragma unroll
        for (int off = 16; off > 0; off >>= 1)
            r += __shfl_down_sync(0xffffffffu, r, off);
        if (lane == 0) g_bsum[b] = r;
    }
}

__global__ __launch_bounds__(128) void scanB_kernel() {
    __shared__ int sh[128];
    const int t = threadIdx.x;
    int v = (t < SCAN_BLK) ? g_bsum[t] : 0;
    sh[t] = v;
    __syncthreads();
#pragma unroll
    for (int off = 1; off < 128; off <<= 1) {
        int y = (t >= off) ? sh[t - off] : 0;
        __syncthreads();
        sh[t] += y;
        __syncthreads();
    }
    if (t < SCAN_BLK) g_bpre[t] = sh[t] - v;
    if (t == 127) g_off[NNODES] = sh[127];
}

__global__ __launch_bounds__(1024) void scanC_kernel() {
    __shared__ int wsum[32];
    const int t = threadIdx.x, b = blockIdx.x;
    const int lane = t & 31, wid = t >> 5;
    int i = b * 1024 + t;
    int v = (i < NNODES) ? g_count[i] : 0;
    int xv = v;
#pragma unroll
    for (int off = 1; off < 32; off <<= 1) {
        int y = __shfl_up_sync(0xffffffffu, xv, off);
        if (lane >= off) xv += y;
    }
    if (lane == 31) wsum[wid] = xv;
    __syncthreads();
    if (wid == 0) {
        int s0 = wsum[lane];
        int s = s0;
#pragma unroll
        for (int off = 1; off < 32; off <<= 1) {
            int y = __shfl_up_sync(0xffffffffu, s, off);
            if (lane >= off) s += y;
        }
        wsum[lane] = s - s0;
    }
    __syncthreads();
    if (i < NNODES) {
        int excl = (xv - v) + wsum[wid] + g_bpre[b];
        g_off[i]    = excl;
        g_cursor[i] = excl;
    }
}

__global__ void reorder_kernel(const int* __restrict__ esrc,
                               const int* __restrict__ edst,
                               const float* __restrict__ ew, int E)
{
    int e = blockIdx.x * blockDim.x + threadIdx.x;
    if (e < E) {
        int d = edst[e];
        int pos = atomicAdd(&g_cursor[d], 1);
        g_edge_s[pos] = make_int2(esrc[e], __float_as_int(ew[e]));
    }
}

// ---------------- aggregation: 1 warp per dst node, fp16 gather ------------
__global__ __launch_bounds__(256) void agg_kernel(float* __restrict__ out, int N)
{
    int node = blockIdx.x * 8 + (threadIdx.x >> 5);
    int lane = threadIdx.x & 31;
    if (node >= N) return;

    int beg = g_off[node];
    int end = g_off[node + 1];

    float a[8] = {0.f, 0.f, 0.f, 0.f, 0.f, 0.f, 0.f, 0.f};

    for (int j = beg; j < end; j += 32) {
        int n = min(32, end - j);
        int2 e = (lane < n) ? __ldg(&g_edge_s[j + lane]) : make_int2(0, 0);
        for (int t = 0; t < n; ++t) {
            int   s = __shfl_sync(0xffffffffu, e.x, t);
            float w = __int_as_float(__shfl_sync(0xffffffffu, e.y, t));
            const uint4* hp = (const uint4*)(g_h + (size_t)s * DOUT);
            uint4 u = __ldg(hp + lane);
            float2 f0 = __half22float2(*(__half2*)&u.x);
            float2 f1 = __half22float2(*(__half2*)&u.y);
            float2 f2 = __half22float2(*(__half2*)&u.z);
            float2 f3 = __half22float2(*(__half2*)&u.w);
            a[0] = fmaf(w, f0.x, a[0]); a[1] = fmaf(w, f0.y, a[1]);
            a[2] = fmaf(w, f1.x, a[2]); a[3] = fmaf(w, f1.y, a[3]);
            a[4] = fmaf(w, f2.x, a[4]); a[5] = fmaf(w, f2.y, a[5]);
            a[6] = fmaf(w, f3.x, a[6]); a[7] = fmaf(w, f3.y, a[7]);
        }
    }

#pragma unroll
    for (int i = 0; i < 8; ++i) a[i] = fmaxf(a[i], 0.f);

    float* op = out + (size_t)node * DOUT + lane * 8;
    *(float4*)(op)     = make_float4(a[0], a[1], a[2], a[3]);
    *(float4*)(op + 4) = make_float4(a[4], a[5], a[6], a[7]);
}

// ---------------- launch: fork-join graph (GEMM || CSR build) --------------
extern "C" void kernel_launch(void* const* d_in, const int* in_sizes, int n_in,
                              void* d_out, int out_size)
{
    const float* x    = (const float*)d_in[0];
    const float* W    = (const float*)d_in[1];
    const int*   esrc = (const int*)d_in[2];
    const int*   edst = (const int*)d_in[3];
    const float* ew   = (const float*)d_in[4];
    float*       out  = (float*)d_out;

    const int M = in_sizes[0] / DIN;   // 100000
    const int E = in_sizes[2];         // 3200000

    // one-time side stream + events (created on first, non-captured call)
    static cudaStream_t s2 = nullptr;
    static cudaEvent_t  evF = nullptr, evJ = nullptr;
    if (!s2) {
        cudaStreamCreateWithFlags(&s2, cudaStreamNonBlocking);
        cudaEventCreateWithFlags(&evF, cudaEventDisableTiming);
        cudaEventCreateWithFlags(&evJ, cudaEventDisableTiming);
    }

    // fork: side stream joins the captured graph
    cudaEventRecord(evF, 0);
    cudaStreamWaitEvent(s2, evF, 0);

    // branch A (main stream): W split + GEMM (tensor/ALU-bound)
    wsplit_kernel<<<(DOUT * DIN + 255) / 256, 256>>>(W);
    gemm_wmma_kernel<<<(M + BMT - 1) / BMT, 256>>>(x, M);

    // branch B (side stream): CSR build (LTS/atomic-bound)
    zero_count_kernel<<<(NNODES + 255) / 256, 256, 0, s2>>>();
    hist_kernel<<<(E + 255) / 256, 256, 0, s2>>>(edst, E);
    scanA_kernel<<<SCAN_BLK, 1024, 0, s2>>>();
    scanB_kernel<<<1, 128, 0, s2>>>();
    scanC_kernel<<<SCAN_BLK, 1024, 0, s2>>>();
    reorder_kernel<<<(E + 255) / 256, 256, 0, s2>>>(esrc, edst, ew, E);

    // join: agg needs both h and the CSR
    cudaEventRecord(evJ, s2);
    cudaStreamWaitEvent(0, evJ, 0);

    agg_kernel<<<(M + 7) / 8, 256>>>(out, M);
}

// round 17
// speedup vs baseline: 2.4905x; 1.7404x over previous
#include <cuda_runtime.h>
#include <cuda_fp16.h>
#include <mma.h>
#include <cstdint>

using namespace nvcuda;

// ---------------- problem constants ----------------
#define NNODES   100000
#define DIN      512
#define DOUT     256
#define EDGES_MAX 3200000
#define KEEP_THRESH 7549747u          // 0.9f == 7549747 * 2^-23 exactly
#define INV_KEEP (1.0f/0.9f)
#define SCAN_BLK  98

// GEMM tiling (wmma HMMA fp16 path, compute_103-safe)
#define BMT 64
#define BNT 256
#define KC  32
#define NCHUNK (DIN / KC)             // 16
#define LDS_T 40                      // 80B row stride — MULTIPLE OF 8 ELEMENTS
                                      // (wmma ldm contract for 16-bit types; 36 broke
                                      //  the fp16/LDSM path with misaligned rows)

// scratch — vector-accessed globals keep explicit 256B base alignment
__device__ __align__(256) __half  g_h[(size_t)NNODES * DOUT];   // 51.2 MB fp16
__device__ __align__(256) __half  g_Bh[DOUT * DIN];             // W fp16, K-major [n][k]
__device__ __align__(256) int2    g_edge_s[EDGES_MAX];
__device__ int     g_count[NNODES];
__device__ int     g_off[NNODES + 1];
__device__ int     g_cursor[NNODES];
__device__ int     g_bsum[SCAN_BLK];
__device__ int     g_bpre[SCAN_BLK];

// ---------------- JAX threefry2x32, partitionable layout (key = (0,42)) ----
__device__ __forceinline__ uint32_t rotl32(uint32_t x, int r) {
    return __funnelshift_l(x, x, r);
}

__device__ __forceinline__ uint32_t threefry_bits(uint32_t idx) {
    const uint32_t ks0 = 0u;
    const uint32_t ks1 = 42u;
    const uint32_t ks2 = 0x1BD11BDAu ^ 42u;
    uint32_t x0 = 0u;
    uint32_t x1 = idx;
    x0 += ks0; x1 += ks1;
#define TFR(r) { x0 += x1; x1 = rotl32(x1, r); x1 ^= x0; }
    TFR(13) TFR(15) TFR(26) TFR(6)   x0 += ks1; x1 += ks2 + 1u;
    TFR(17) TFR(29) TFR(16) TFR(24)  x0 += ks2; x1 += ks0 + 2u;
    TFR(13) TFR(15) TFR(26) TFR(6)   x0 += ks0; x1 += ks1 + 3u;
    TFR(17) TFR(29) TFR(16) TFR(24)  x0 += ks1; x1 += ks2 + 4u;
    TFR(13) TFR(15) TFR(26) TFR(6)   x0 += ks2; x1 += ks0 + 5u;
#undef TFR
    return x0 ^ x1;
}

__device__ __forceinline__ float dropout_val(float v, uint32_t idx) {
    uint32_t m = threefry_bits(idx) >> 9;
    return (m < KEEP_THRESH) ? v * INV_KEEP : 0.0f;
}

// ---------------- kernel 0: W fp32 -> fp16, K-major [n][k] ----------------
__global__ void wconv_kernel(const float* __restrict__ W) {
    int i = blockIdx.x * blockDim.x + threadIdx.x;
    if (i < DOUT * DIN) {
        int n = i >> 9;           // /DIN
        int k = i & (DIN - 1);
        g_Bh[i] = __float2half_rn(W[(size_t)k * DOUT + n]);
    }
}

// ---------------- kernel 1: dropout + fp16 wmma GEMM (single product) ------
// occ=2 CTAs/SM. CTA 64x256, 8 warps 2(M)x4(N), warp tile 32x64.
__global__ void __launch_bounds__(256, 2) gemm_wmma_kernel(
    const float* __restrict__ x, int M)
{
    __shared__ __align__(32) __half Ah[BMT][LDS_T];
    __shared__ __align__(32) __half Bh[BNT][LDS_T];   // [n][k]

    const int tid  = threadIdx.x;
    const int wid  = tid >> 5;
    const int lane = tid & 31;
    const int wm = wid & 1;              // M offset wm*32
    const int wn = wid >> 1;             // N offset wn*64
    const int bm = blockIdx.x * BMT;

    const int arow = tid >> 2;                 // 0..63
    const int akof = (tid & 3) * 8;            // 0,8,16,24
    const int grow = bm + arow;
    const bool rok = (grow < M);

    wmma::fragment<wmma::accumulator, 16, 16, 16, float> c[2][4];
#pragma unroll
    for (int i = 0; i < 2; ++i)
#pragma unroll
        for (int j = 0; j < 4; ++j) wmma::fill_fragment(c[i][j], 0.0f);

    for (int ch = 0; ch < NCHUNK; ++ch) {
        const int k0 = ch * KC;

        // ---- A: dropout -> fp16 ----
        {
            float f[8];
            if (rok) {
                const float* xp = x + (size_t)grow * DIN + k0 + akof;
                float4 v0 = *(const float4*)(xp);
                float4 v1 = *(const float4*)(xp + 4);
                uint32_t base = (uint32_t)grow * DIN + (uint32_t)(k0 + akof);
                f[0] = dropout_val(v0.x, base);
                f[1] = dropout_val(v0.y, base + 1u);
                f[2] = dropout_val(v0.z, base + 2u);
                f[3] = dropout_val(v0.w, base + 3u);
                f[4] = dropout_val(v1.x, base + 4u);
                f[5] = dropout_val(v1.y, base + 5u);
                f[6] = dropout_val(v1.z, base + 6u);
                f[7] = dropout_val(v1.w, base + 7u);
            } else {
#pragma unroll
                for (int q = 0; q < 8; ++q) f[q] = 0.f;
            }
            // akof is a multiple of 8 -> tid*80B + akof*2B is 16B-aligned
            __half2 h0 = __floats2half2_rn(f[0], f[1]);
            __half2 h1 = __floats2half2_rn(f[2], f[3]);
            __half2 h2 = __floats2half2_rn(f[4], f[5]);
            __half2 h3 = __floats2half2_rn(f[6], f[7]);
            uint4 u;
            u.x = *(uint32_t*)&h0; u.y = *(uint32_t*)&h1;
            u.z = *(uint32_t*)&h2; u.w = *(uint32_t*)&h3;
            *(uint4*)&Ah[arow][akof] = u;
        }

        // ---- B: load fp16 plane (L2-resident, 256KB); 16B smem stores ----
        {
            const __half* ph = g_Bh + (size_t)tid * DIN + k0;
#pragma unroll
            for (int q = 0; q < 4; ++q) {
                uint4 vh = __ldg((const uint4*)(ph) + q);   // 8 halves
                *(uint4*)&Bh[tid][q * 8] = vh;              // tid*80 + q*16 : 16B ok
            }
        }
        __syncthreads();

        // ---- MMA: 2 ksteps x (2x4 tiles), single product ----
#pragma unroll
        for (int ks = 0; ks < 2; ++ks) {
            wmma::fragment<wmma::matrix_a, 16, 16, 16, __half, wmma::row_major> ah[2];
            wmma::fragment<wmma::matrix_b, 16, 16, 16, __half, wmma::col_major> bh[4];
#pragma unroll
            for (int i = 0; i < 2; ++i)
                wmma::load_matrix_sync(ah[i], &Ah[wm*32 + i*16][ks*16], LDS_T);
#pragma unroll
            for (int j = 0; j < 4; ++j)
                wmma::load_matrix_sync(bh[j], &Bh[wn*64 + j*16][ks*16], LDS_T);
#pragma unroll
            for (int i = 0; i < 2; ++i)
#pragma unroll
                for (int j = 0; j < 4; ++j)
                    wmma::mma_sync(c[i][j], ah[i], bh[j], c[i][j]);
        }
        __syncthreads();
    }

    // ---- epilogue: per-warp 16x16 fp32 patch (in Bh region) -> fp16 g_h ----
    float* patch = (float*)&Bh[0][0] + wid * 256;   // 1KB per warp, 32B-aligned
    const int prow = lane >> 1;
    const int pcol = (lane & 1) * 8;

#pragma unroll
    for (int i = 0; i < 2; ++i)
#pragma unroll
        for (int j = 0; j < 4; ++j) {
            wmma::store_matrix_sync(patch, c[i][j], 16, wmma::mem_row_major);
            __syncwarp();
            int orow = bm + wm*32 + i*16 + prow;
            if (orow < M) {
                const float* pr = patch + prow * 16 + pcol;
                __half2 p0 = __floats2half2_rn(pr[0], pr[1]);
                __half2 p1 = __floats2half2_rn(pr[2], pr[3]);
                __half2 p2 = __floats2half2_rn(pr[4], pr[5]);
                __half2 p3 = __floats2half2_rn(pr[6], pr[7]);
                uint4 u;
                u.x = *(uint32_t*)&p0; u.y = *(uint32_t*)&p1;
                u.z = *(uint32_t*)&p2; u.w = *(uint32_t*)&p3;
                *(uint4*)(g_h + (size_t)orow * DOUT + wn*64 + j*16 + pcol) = u;
            }
            __syncwarp();
        }
}

// ---------------- CSR build ----------------
__global__ void zero_count_kernel() {
    int i = blockIdx.x * blockDim.x + threadIdx.x;
    if (i < NNODES) g_count[i] = 0;
}

__global__ void hist_kernel(const int* __restrict__ edst, int E) {
    int e = blockIdx.x * blockDim.x + threadIdx.x;
    if (e < E) atomicAdd(&g_count[edst[e]], 1);
}

__global__ __launch_bounds__(1024) void scanA_kernel() {
    __shared__ int wsum[32];
    const int t = threadIdx.x, b = blockIdx.x;
    const int lane = t & 31, wid = t >> 5;
    int i = b * 1024 + t;
    int v = (i < NNODES) ? g_count[i] : 0;
    int s = v;
#pragma unroll
    for (int off = 16; off > 0; off >>= 1)
        s += __shfl_down_sync(0xffffffffu, s, off);
    if (lane == 0) wsum[wid] = s;
    __syncthreads();
    if (wid == 0) {
        int r = wsum[lane];
#pragma unroll
        for (int off = 16; off > 0; off >>= 1)
            r += __shfl_down_sync(0xffffffffu, r, off);
        if (lane == 0) g_bsum[b] = r;
    }
}

__global__ __launch_bounds__(128) void scanB_kernel() {
    __shared__ int sh[128];
    const int t = threadIdx.x;
    int v = (t < SCAN_BLK) ? g_bsum[t] : 0;
    sh[t] = v;
    __syncthreads();
#pragma unroll
    for (int off = 1; off < 128; off <<= 1) {
        int y = (t >= off) ? sh[t - off] : 0;
        __syncthreads();
        sh[t] += y;
        __syncthreads();
    }
    if (t < SCAN_BLK) g_bpre[t] = sh[t] - v;
    if (t == 127) g_off[NNODES] = sh[127];
}

__global__ __launch_bounds__(1024) void scanC_kernel() {
    __shared__ int wsum[32];
    const int t = threadIdx.x, b = blockIdx.x;
    const int lane = t & 31, wid = t >> 5;
    int i = b * 1024 + t;
    int v = (i < NNODES) ? g_count[i] : 0;
    int xv = v;
#pragma unroll
    for (int off = 1; off < 32; off <<= 1) {
        int y = __shfl_up_sync(0xffffffffu, xv, off);
        if (lane >= off) xv += y;
    }
    if (lane == 31) wsum[wid] = xv;
    __syncthreads();
    if (wid == 0) {
        int s0 = wsum[lane];
        int s = s0;
#pragma unroll
        for (int off = 1; off < 32; off <<= 1) {
            int y = __shfl_up_sync(0xffffffffu, s, off);
            if (lane >= off) s += y;
        }
        wsum[lane] = s - s0;
    }
    __syncthreads();
    if (i < NNODES) {
        int excl = (xv - v) + wsum[wid] + g_bpre[b];
        g_off[i]    = excl;
        g_cursor[i] = excl;
    }
}

__global__ void reorder_kernel(const int* __restrict__ esrc,
                               const int* __restrict__ edst,
                               const float* __restrict__ ew, int E)
{
    int e = blockIdx.x * blockDim.x + threadIdx.x;
    if (e < E) {
        int d = edst[e];
        int pos = atomicAdd(&g_cursor[d], 1);
        g_edge_s[pos] = make_int2(esrc[e], __float_as_int(ew[e]));
    }
}

// ---------------- aggregation: 1 warp per dst node, fp16 gather ------------
__global__ __launch_bounds__(256) void agg_kernel(float* __restrict__ out, int N)
{
    int node = blockIdx.x * 8 + (threadIdx.x >> 5);
    int lane = threadIdx.x & 31;
    if (node >= N) return;

    int beg = g_off[node];
    int end = g_off[node + 1];

    float a[8] = {0.f, 0.f, 0.f, 0.f, 0.f, 0.f, 0.f, 0.f};

    for (int j = beg; j < end; j += 32) {
        int n = min(32, end - j);
        int2 e = (lane < n) ? __ldg(&g_edge_s[j + lane]) : make_int2(0, 0);
        for (int t = 0; t < n; ++t) {
            int   s = __shfl_sync(0xffffffffu, e.x, t);
            float w = __int_as_float(__shfl_sync(0xffffffffu, e.y, t));
            const uint4* hp = (const uint4*)(g_h + (size_t)s * DOUT);
            uint4 u = __ldg(hp + lane);
            float2 f0 = __half22float2(*(__half2*)&u.x);
            float2 f1 = __half22float2(*(__half2*)&u.y);
            float2 f2 = __half22float2(*(__half2*)&u.z);
            float2 f3 = __half22float2(*(__half2*)&u.w);
            a[0] = fmaf(w, f0.x, a[0]); a[1] = fmaf(w, f0.y, a[1]);
            a[2] = fmaf(w, f1.x, a[2]); a[3] = fmaf(w, f1.y, a[3]);
            a[4] = fmaf(w, f2.x, a[4]); a[5] = fmaf(w, f2.y, a[5]);
            a[6] = fmaf(w, f3.x, a[6]); a[7] = fmaf(w, f3.y, a[7]);
        }
    }

#pragma unroll
    for (int i = 0; i < 8; ++i) a[i] = fmaxf(a[i], 0.f);

    float* op = out + (size_t)node * DOUT + lane * 8;
    *(float4*)(op)     = make_float4(a[0], a[1], a[2], a[3]);
    *(float4*)(op + 4) = make_float4(a[4], a[5], a[6], a[7]);
}

// ---------------- launch: fork-join graph (GEMM || CSR build) --------------
extern "C" void kernel_launch(void* const* d_in, const int* in_sizes, int n_in,
                              void* d_out, int out_size)
{
    const float* x    = (const float*)d_in[0];
    const float* W    = (const float*)d_in[1];
    const int*   esrc = (const int*)d_in[2];
    const int*   edst = (const int*)d_in[3];
    const float* ew   = (const float*)d_in[4];
    float*       out  = (float*)d_out;

    const int M = in_sizes[0] / DIN;   // 100000
    const int E = in_sizes[2];         // 3200000

    // one-time side stream + events (created on first, non-captured call)
    static cudaStream_t s2 = nullptr;
    static cudaEvent_t  evF = nullptr, evJ = nullptr;
    if (!s2) {
        cudaStreamCreateWithFlags(&s2, cudaStreamNonBlocking);
        cudaEventCreateWithFlags(&evF, cudaEventDisableTiming);
        cudaEventCreateWithFlags(&evJ, cudaEventDisableTiming);
    }

    // fork: side stream joins the captured graph
    cudaEventRecord(evF, 0);
    cudaStreamWaitEvent(s2, evF, 0);

    // branch A (main stream): W convert + fp16 GEMM (tensor/ALU-bound)
    wconv_kernel<<<(DOUT * DIN + 255) / 256, 256>>>(W);
    gemm_wmma_kernel<<<(M + BMT - 1) / BMT, 256>>>(x, M);

    // branch B (side stream): CSR build (LTS/atomic-bound)
    zero_count_kernel<<<(NNODES + 255) / 256, 256, 0, s2>>>();
    hist_kernel<<<(E + 255) / 256, 256, 0, s2>>>(edst, E);
    scanA_kernel<<<SCAN_BLK, 1024, 0, s2>>>();
    scanB_kernel<<<1, 128, 0, s2>>>();
    scanC_kernel<<<SCAN_BLK, 1024, 0, s2>>>();
    reorder_kernel<<<(E + 255) / 256, 256, 0, s2>>>(esrc, edst, ew, E);

    // join: agg needs both h and the CSR
    cudaEventRecord(evJ, s2);
    cudaStreamWaitEvent(0, evJ, 0);

    agg_kernel<<<(M + 7) / 8, 256>>>(out, M);
}